// round 2
// baseline (speedup 1.0000x reference)
#include <cuda_runtime.h>

#define C_IN   64
#define C_OUT  64
#define HWDIM  224
#define BATCH  8
#define NPIX   (BATCH * HWDIM * HWDIM)   /* per-channel count: 401408 */
#define EPS_BN 1e-5f
#define LEAK   0.1f
#define CEILV  255.0f

// ---------------- device scratch (no allocations allowed) ----------------
__device__ __align__(16) float  g_weff[C_IN * 9 * C_OUT];   // layout [i][k][o]
__device__ double g_sum  [C_OUT];
__device__ double g_sumsq[C_OUT];
__device__ float  g_scale[C_OUT];
__device__ float  g_shift[C_OUT];

// ---------------- kernel A: fold 3x3-ternary + 1x1 into dense 3x3 --------
// Weff[o,i,k] = sum_m w1x1[o,m] * w_bin[m,i,k]; also zero stat accumulators.
__global__ void fold_kernel(const float* __restrict__ w1x1,
                            const float* __restrict__ w_bin) {
    int t = blockIdx.x * blockDim.x + threadIdx.x;
    if (t < C_OUT) { g_sum[t] = 0.0; g_sumsq[t] = 0.0; }
    if (t >= C_IN * 9 * C_OUT) return;
    int o = t & 63;
    int k = (t >> 6) % 9;
    int i = t / (9 * 64);
    float s = 0.f;
    #pragma unroll 8
    for (int m = 0; m < C_IN; ++m)
        s += w1x1[o * C_IN + m] * w_bin[(m * C_IN + i) * 9 + k];
    g_weff[(i * 9 + k) * 64 + o] = s;
}

// ---------------- kernel B: dense 3x3 conv + bias + BN-stat accumulation -
// Block: 256 threads = 4 output-channel groups (16 ch) x 64 pixel slots.
// Pixel tile: 16x16; each slot owns 4 consecutive columns.
__global__ __launch_bounds__(256, 2)
void conv_kernel(const float* __restrict__ x,
                 const float* __restrict__ bias,
                 float* __restrict__ out) {
    __shared__ __align__(16) float xs[18 * 19];  // 18x18 input tile, stride 19
    __shared__ __align__(16) float ws[9 * 64];   // weights for cur in-ch, [k][o]
    __shared__ float s_sum[C_OUT];
    __shared__ float s_ssq[C_OUT];

    const int tid  = threadIdx.x;
    const int b    = blockIdx.z;
    const int bx   = blockIdx.x, by = blockIdx.y;
    const int og   = tid >> 6;            // 0..3  (16 output channels each)
    const int slot = tid & 63;            // 0..63
    const int srow = slot >> 2;           // 0..15
    const int scol = (slot & 3) * 4;      // 0,4,8,12

    if (tid < C_OUT) { s_sum[tid] = 0.f; s_ssq[tid] = 0.f; }

    float acc[16][4];
    #pragma unroll
    for (int j = 0; j < 16; ++j)
        #pragma unroll
        for (int p = 0; p < 4; ++p) acc[j][p] = 0.f;

    const int row_g0 = by * 16 - 1;
    const int col_g0 = bx * 16 - 1;
    const float* xb = x + (size_t)b * C_IN * HWDIM * HWDIM;

    for (int i = 0; i < C_IN; ++i) {
        __syncthreads();  // protect xs/ws from previous iteration's readers
        // load 18x18 input tile (zero-padded at borders)
        const float* xp = xb + (size_t)i * (HWDIM * HWDIM);
        for (int idx = tid; idx < 18 * 18; idx += 256) {
            int r = idx / 18, c = idx - r * 18;
            int gr = row_g0 + r, gc = col_g0 + c;
            float v = 0.f;
            if ((unsigned)gr < HWDIM && (unsigned)gc < HWDIM) v = xp[gr * HWDIM + gc];
            xs[r * 19 + c] = v;
        }
        // load this input channel's 9x64 weight slice
        const float* wp = g_weff + i * 576;
        for (int idx = tid; idx < 576; idx += 256) ws[idx] = wp[idx];
        __syncthreads();

        // register window of 3x6 input values covering 4 pixels x 3 taps
        float xr[3][6];
        #pragma unroll
        for (int kh = 0; kh < 3; ++kh)
            #pragma unroll
            for (int m = 0; m < 6; ++m)
                xr[kh][m] = xs[(srow + kh) * 19 + scol + m];

        #pragma unroll
        for (int kh = 0; kh < 3; ++kh) {
            #pragma unroll
            for (int kw = 0; kw < 3; ++kw) {
                const float4* wv =
                    (const float4*)&ws[(kh * 3 + kw) * 64 + og * 16];
                #pragma unroll
                for (int jj = 0; jj < 4; ++jj) {
                    float4 w4 = wv[jj];
                    #pragma unroll
                    for (int p = 0; p < 4; ++p) {
                        acc[jj * 4 + 0][p] += w4.x * xr[kh][kw + p];
                        acc[jj * 4 + 1][p] += w4.y * xr[kh][kw + p];
                        acc[jj * 4 + 2][p] += w4.z * xr[kh][kw + p];
                        acc[jj * 4 + 3][p] += w4.w * xr[kh][kw + p];
                    }
                }
            }
        }
    }

    // epilogue: bias, per-channel partial stats, coalesced float4 store
    const int row = by * 16 + srow;
    const int col = bx * 16 + scol;
    #pragma unroll
    for (int j = 0; j < 16; ++j) {
        int o = og * 16 + j;
        float bv = bias[o];
        float4 v;
        float* vp = &v.x;
        float s = 0.f, ss = 0.f;
        #pragma unroll
        for (int p = 0; p < 4; ++p) {
            float y = acc[j][p] + bv;
            vp[p] = y;
            s  += y;
            ss += y * y;
        }
        atomicAdd(&s_sum[o], s);
        atomicAdd(&s_ssq[o], ss);
        *(float4*)(out + ((size_t)(b * C_OUT + o) * HWDIM + row) * HWDIM + col) = v;
    }
    __syncthreads();
    if (tid < C_OUT) {
        atomicAdd(&g_sum[tid],   (double)s_sum[tid]);
        atomicAdd(&g_sumsq[tid], (double)s_ssq[tid]);
    }
}

// ---------------- kernel C: finalize BN affine params --------------------
__global__ void stats_kernel(const float* __restrict__ gamma,
                             const float* __restrict__ beta) {
    int c = threadIdx.x;
    if (c >= C_OUT) return;
    double m = g_sum[c]   / (double)NPIX;
    double v = g_sumsq[c] / (double)NPIX - m * m;
    float a = gamma[c] * rsqrtf((float)v + EPS_BN);
    g_scale[c] = a;
    g_shift[c] = beta[c] - (float)m * a;
}

// ---------------- kernel D: normalize + leaky relu + clamp (in place) ----
__global__ void act_kernel(float* __restrict__ out) {
    int idx = blockIdx.x * blockDim.x + threadIdx.x;
    const int total4 = BATCH * C_OUT * HWDIM * HWDIM / 4;
    if (idx >= total4) return;
    int plane = (idx * 4) / (HWDIM * HWDIM);   // b*64 + o
    int c = plane & 63;
    float a  = g_scale[c];
    float sh = g_shift[c];
    float4 v = ((float4*)out)[idx];
    float* vp = &v.x;
    #pragma unroll
    for (int p = 0; p < 4; ++p) {
        float y = a * vp[p] + sh;
        y = (y >= 0.f) ? y : LEAK * y;
        y = fminf(fmaxf(y, 0.f), CEILV);
        vp[p] = y;
    }
    ((float4*)out)[idx] = v;
}

// ---------------- launch ---------------------------------------------------
extern "C" void kernel_launch(void* const* d_in, const int* in_sizes, int n_in,
                              void* d_out, int out_size) {
    const float* x     = (const float*)d_in[0];
    const float* w_bin = (const float*)d_in[1];
    const float* w1x1  = (const float*)d_in[2];
    const float* b1x1  = (const float*)d_in[3];
    const float* gamma = (const float*)d_in[4];
    const float* beta  = (const float*)d_in[5];
    float* out = (float*)d_out;

    fold_kernel<<<(C_IN * 9 * C_OUT + 255) / 256, 256>>>(w1x1, w_bin);

    dim3 grid(HWDIM / 16, HWDIM / 16, BATCH);   // 14 x 14 x 8
    conv_kernel<<<grid, 256>>>(x, b1x1, out);

    stats_kernel<<<1, 64>>>(gamma, beta);

    int total4 = BATCH * C_OUT * HWDIM * HWDIM / 4;
    act_kernel<<<(total4 + 255) / 256, 256>>>(out);
}

// round 4
// speedup vs baseline: 3.5205x; 3.5205x over previous
#include <cuda_runtime.h>
#include <cstdint>

#define C64    64
#define HW     224
#define HP     226
#define NB     8
#define NPIX   (NB * HW * HW)
#define EPS_BN 1e-5f
#define LEAK   0.1f
#define CEILV  255.0f

#define NTILE  3584            /* 8 b * 224 h * 2 wseg */
#define NCTA   148

// SMEM float-index layout
#define SM_BIAS 0              /* 64 floats */
#define SM_B    128            /* 72*64*9 = 41472 floats (tf32 weights, pad 9) */
#define SM_A    (128 + 41472)  /* 3*130*36 = 14040 floats */
#define SM_FLTS (128 + 41472 + 14040)
#define SMEM_DYN (SM_FLTS * 4) /* 222560 B */

// ---------------- device scratch ----------------
__device__ float  g_xpad[NB * HP * HP * C64];   // padded NHWC (~105MB)
__device__ float  g_wB[72 * 64 * 9];            // [kstep][o][k8] tf32, pad 9
__device__ double g_sum[C64];
__device__ double g_ssq[C64];
__device__ float  g_scale[C64];
__device__ float  g_shift[C64];

static __device__ __forceinline__ uint32_t tf32_rna(float x) {
    uint32_t u;
    asm("cvt.rna.tf32.f32 %0, %1;" : "=r"(u) : "f"(x));
    return u;
}

static __device__ __forceinline__ void mma8(float* d, const uint32_t* a,
                                            const uint32_t* b) {
    asm volatile(
        "mma.sync.aligned.m16n8k8.row.col.f32.tf32.tf32.f32 "
        "{%0,%1,%2,%3},{%4,%5,%6,%7},{%8,%9},{%0,%1,%2,%3};"
        : "+f"(d[0]), "+f"(d[1]), "+f"(d[2]), "+f"(d[3])
        : "r"(a[0]), "r"(a[1]), "r"(a[2]), "r"(a[3]), "r"(b[0]), "r"(b[1]));
}

// ---------------- kernel: fold 3x3-ternary + 1x1, emit tf32 --------------
__global__ void fold_k(const float* __restrict__ w1x1,
                       const float* __restrict__ w_bin) {
    int t = blockIdx.x * 256 + threadIdx.x;
    if (t < C64) { g_sum[t] = 0.0; g_ssq[t] = 0.0; }
    if (t >= 64 * 9 * 64) return;
    int o = t & 63;
    int k = (t >> 6) % 9;        // tap
    int i = t / 576;             // in channel
    float s = 0.f;
    #pragma unroll 8
    for (int m = 0; m < 64; ++m)
        s += w1x1[o * 64 + m] * w_bin[(m * 64 + i) * 9 + k];
    // kstep = tap*8 + i/8 ; slot = i%8
    g_wB[((k * 8 + (i >> 3)) * 64 + o) * 9 + (i & 7)] =
        __uint_as_float(tf32_rna(s));
}

// ---------------- kernel: zero padded border ----------------
__global__ void pad_zero() {
    int p = blockIdx.x;      // 0..899
    int b = blockIdx.y;
    int hp, wp;
    if (p < 226)      { hp = 0;   wp = p; }
    else if (p < 452) { hp = 225; wp = p - 226; }
    else { int q = p - 452; hp = 1 + (q >> 1); wp = (q & 1) * 225; }
    g_xpad[(((size_t)b * HP + hp) * HP + wp) * 64 + threadIdx.x] = 0.f;
}

// ---------------- kernel: NCHW -> padded NHWC (tf32-rounded) -------------
__global__ void pad_tr(const float* __restrict__ x) {
    __shared__ float s[64][33];
    int lx = threadIdx.x, ly = threadIdx.y;   // 32, 8
    int w0 = blockIdx.x * 32, h = blockIdx.y, b = blockIdx.z;
    #pragma unroll
    for (int i = 0; i < 8; ++i) {
        int c = i * 8 + ly;
        s[c][lx] = x[(((size_t)b * 64 + c) * HW + h) * HW + w0 + lx];
    }
    __syncthreads();
    float* dst = g_xpad + (((size_t)b * HP + h + 1) * HP + w0 + 1) * 64;
    #pragma unroll
    for (int jj = 0; jj < 8; ++jj) {
        int f = jj * 256 + ly * 32 + lx;
        int ch = f & 63, px = f >> 6;
        dst[(size_t)px * 64 + ch] = __uint_as_float(tf32_rna(s[ch][px]));
    }
}

// ---------------- kernel: tf32 mma.sync implicit-GEMM conv ---------------
// Persistent: 148 CTAs x 256 thr. Tile D[128px x 64oc], K = 9 taps x 64ch.
// Warps 4(m) x 2(n); warp tile 32x32 = 2 m16 x 4 n8.
__global__ __launch_bounds__(256, 1)
void conv_mma(const float* __restrict__ bias, float* __restrict__ out) {
    extern __shared__ __align__(16) float sm[];
    float* Bs = sm + SM_B;
    float* As = sm + SM_A;
    const int tid = threadIdx.x;
    const int lane = tid & 31, wid = tid >> 5;
    const int wm = wid & 3, wn = wid >> 2;
    const int gr = lane >> 2, gc = lane & 3;

    // weights + bias -> SMEM once
    for (int i = tid; i < 41472; i += 256) Bs[i] = g_wB[i];
    if (tid < 64) sm[SM_BIAS + tid] = bias[tid];

    const int aoff = (wm * 32 + gr) * 36 + gc;       // A frag lane base
    const int boff = (wn * 32 + gr) * 9  + gc;       // B frag lane base

    for (int j = 0; j < 25; ++j) {
        int t = j * NCTA + blockIdx.x;
        if (t >= NTILE) break;
        int b  = t / 448, rr = t % 448;
        int h  = rr >> 1, w0 = (rr & 1) * 96;
        const float* xrow = g_xpad + (((size_t)b * HP + h) * HP + w0) * 64;

        float acc[2][4][4];
        #pragma unroll
        for (int ms = 0; ms < 2; ++ms)
            #pragma unroll
            for (int ns = 0; ns < 4; ++ns)
                #pragma unroll
                for (int q = 0; q < 4; ++q) acc[ms][ns][q] = 0.f;

        #pragma unroll
        for (int pl = 0; pl < 2; ++pl) {
            __syncthreads();   // previous readers done
            // stage A: 3 rows x 130 px x 32 ch, px-stride 36 floats
            for (int i = tid; i < 3120; i += 256) {
                int r = i / 1040, rem = i % 1040;
                int px = rem >> 3, c4 = rem & 7;
                float4 v = *(const float4*)(xrow + ((size_t)r * HP + px) * 64
                                            + pl * 32 + c4 * 4);
                *(float4*)&As[(r * 130 + px) * 36 + c4 * 4] = v;
            }
            __syncthreads();

            #pragma unroll
            for (int kh = 0; kh < 3; ++kh) {
                #pragma unroll
                for (int kw = 0; kw < 3; ++kw) {
                    const int abase = aoff + (kh * 130 + kw) * 36;
                    const int kg = (kh * 3 + kw) * 8 + pl * 4;
                    #pragma unroll
                    for (int ks = 0; ks < 4; ++ks) {
                        uint32_t A0[4], A1[4];
                        const float* ap = As + abase + ks * 8;
                        A0[0] = __float_as_uint(ap[0]);
                        A0[1] = __float_as_uint(ap[8 * 36]);
                        A0[2] = __float_as_uint(ap[4]);
                        A0[3] = __float_as_uint(ap[8 * 36 + 4]);
                        A1[0] = __float_as_uint(ap[16 * 36]);
                        A1[1] = __float_as_uint(ap[24 * 36]);
                        A1[2] = __float_as_uint(ap[16 * 36 + 4]);
                        A1[3] = __float_as_uint(ap[24 * 36 + 4]);
                        const float* bp = Bs + (kg + ks) * 576 + boff;
                        #pragma unroll
                        for (int ns = 0; ns < 4; ++ns) {
                            uint32_t Bf[2];
                            Bf[0] = __float_as_uint(bp[ns * 72]);
                            Bf[1] = __float_as_uint(bp[ns * 72 + 4]);
                            mma8(acc[0][ns], A0, Bf);
                            mma8(acc[1][ns], A1, Bf);
                        }
                    }
                }
            }
        }

        // epilogue: + bias, scatter to NCHW (8-px sector-aligned segments)
        const size_t chstr = (size_t)HW * HW;
        const int pxb = w0 + wm * 32 + gr;
        const int ob  = wn * 32 + gc * 2;
        float* obase = out + ((size_t)b * 64) * chstr + (size_t)h * HW;
        #pragma unroll
        for (int ms = 0; ms < 2; ++ms) {
            #pragma unroll
            for (int ns = 0; ns < 4; ++ns) {
                int o0 = ob + ns * 8;
                float b0 = sm[SM_BIAS + o0], b1 = sm[SM_BIAS + o0 + 1];
                float* p = obase + (size_t)o0 * chstr + pxb + ms * 16;
                p[0]         = acc[ms][ns][0] + b0;
                p[chstr]     = acc[ms][ns][1] + b1;
                p[8]         = acc[ms][ns][2] + b0;
                p[chstr + 8] = acc[ms][ns][3] + b1;
            }
        }
    }
}

// ---------------- kernel: per-channel sum/sumsq over y ----------------
__global__ void reduce_k(const float* __restrict__ y) {
    int c = blockIdx.x, seg = blockIdx.y;
    float s = 0.f, q = 0.f;
    for (int i = 0; i < 28; ++i) {
        int F = seg * 7168 + i * 256 + threadIdx.x;   // f4 idx 0..100351
        int b = F / 12544, off = F % 12544;
        float4 v = ((const float4*)y)[((size_t)(b * 64 + c)) * 12544 + off];
        s += v.x + v.y + v.z + v.w;
        q += v.x * v.x + v.y * v.y + v.z * v.z + v.w * v.w;
    }
    #pragma unroll
    for (int d = 16; d; d >>= 1) {
        s += __shfl_xor_sync(0xFFFFFFFFu, s, d);
        q += __shfl_xor_sync(0xFFFFFFFFu, q, d);
    }
    __shared__ float ss[8], qq[8];
    if ((threadIdx.x & 31) == 0) { ss[threadIdx.x >> 5] = s; qq[threadIdx.x >> 5] = q; }
    __syncthreads();
    if (threadIdx.x == 0) {
        float S = 0.f, Q = 0.f;
        for (int i = 0; i < 8; ++i) { S += ss[i]; Q += qq[i]; }
        atomicAdd(&g_sum[c], (double)S);
        atomicAdd(&g_ssq[c], (double)Q);
    }
}

// ---------------- kernel: finalize BN ----------------
__global__ void stats_k(const float* __restrict__ gamma,
                        const float* __restrict__ beta) {
    int c = threadIdx.x;
    if (c >= C64) return;
    double m = g_sum[c] / (double)NPIX;
    double v = g_ssq[c] / (double)NPIX - m * m;
    float a = gamma[c] * rsqrtf((float)v + EPS_BN);
    g_scale[c] = a;
    g_shift[c] = beta[c] - (float)m * a;
}

// ---------------- kernel: normalize + leaky relu + clamp ----------------
__global__ void act_k(float* __restrict__ out) {
    int idx = blockIdx.x * blockDim.x + threadIdx.x;
    const int total4 = NB * C64 * HW * HW / 4;
    if (idx >= total4) return;
    int plane = (idx * 4) / (HW * HW);
    int c = plane & 63;
    float a = g_scale[c], sh = g_shift[c];
    float4 v = ((float4*)out)[idx];
    float* vp = &v.x;
    #pragma unroll
    for (int p = 0; p < 4; ++p) {
        float y = a * vp[p] + sh;
        y = (y >= 0.f) ? y : LEAK * y;
        y = fminf(fmaxf(y, 0.f), CEILV);
        vp[p] = y;
    }
    ((float4*)out)[idx] = v;
}

// ---------------- launch ----------------
extern "C" void kernel_launch(void* const* d_in, const int* in_sizes, int n_in,
                              void* d_out, int out_size) {
    const float* x     = (const float*)d_in[0];
    const float* w_bin = (const float*)d_in[1];
    const float* w1x1  = (const float*)d_in[2];
    const float* b1x1  = (const float*)d_in[3];
    const float* gamma = (const float*)d_in[4];
    const float* beta  = (const float*)d_in[5];
    float* out = (float*)d_out;

    cudaFuncSetAttribute(conv_mma, cudaFuncAttributeMaxDynamicSharedMemorySize,
                         SMEM_DYN);

    fold_k<<<(64 * 9 * 64 + 255) / 256, 256>>>(w1x1, w_bin);
    pad_zero<<<dim3(900, NB), 64>>>();
    pad_tr<<<dim3(7, HW, NB), dim3(32, 8)>>>(x);
    conv_mma<<<NCTA, 256, SMEM_DYN>>>(b1x1, out);
    reduce_k<<<dim3(64, 14), 256>>>(out);
    stats_k<<<1, 64>>>(gamma, beta);
    int total4 = NB * C64 * HW * HW / 4;
    act_k<<<(total4 + 255) / 256, 256>>>(out);
}

// round 5
// speedup vs baseline: 3.8390x; 1.0905x over previous
#include <cuda_runtime.h>
#include <cstdint>

#define C64    64
#define HW     224
#define HP     226
#define NB     8
#define NPIX   (NB * HW * HW)
#define EPS_BN 1e-5f
#define LEAK   0.1f
#define CEILV  255.0f

#define NTILE  3584            /* 8 b * 224 h * 2 wseg */
#define NCTA   148

// SMEM float-index layout
#define SM_BIAS 0              /* 64 floats */
#define SM_RED  64             /* 128 floats: sum[64], ssq[64] */
#define SM_B    192            /* 36*64*16 = 36864 floats */
#define SM_A    37056          /* 3*130*48 = 18720 floats */
#define SM_FLTS (37056 + 18720)
#define SMEM_DYN (SM_FLTS * 4) /* 223104 B */

#define PXS     48             /* A pixel stride (floats): 48 mod 32 banks = 16 */
#define AROW    (130 * PXS)

// permutation within each 16-channel group: slot = (c&3)*4 + ((c>>2)&3)
#define PERM16(c) (((c) & ~15) | (((c) & 3) << 2) | (((c) >> 2) & 3))

// ---------------- device scratch ----------------
__device__ __align__(16) float  g_xpad[NB * HP * HP * C64];  // padded NHWC, permuted ch
__device__ __align__(16) float  g_wB[36 * 64 * 16];          // [kpair][o][slot16] tf32
__device__ double g_sum[C64];
__device__ double g_ssq[C64];
__device__ float  g_scale[C64];
__device__ float  g_shift[C64];

static __device__ __forceinline__ uint32_t tf32_rna(float x) {
    uint32_t u;
    asm("cvt.rna.tf32.f32 %0, %1;" : "=r"(u) : "f"(x));
    return u;
}
static __device__ __forceinline__ uint32_t fu(float x) { return __float_as_uint(x); }

static __device__ __forceinline__ void mma8(float* d, const uint32_t* a,
                                            const uint32_t* b) {
    asm volatile(
        "mma.sync.aligned.m16n8k8.row.col.f32.tf32.tf32.f32 "
        "{%0,%1,%2,%3},{%4,%5,%6,%7},{%8,%9},{%0,%1,%2,%3};"
        : "+f"(d[0]), "+f"(d[1]), "+f"(d[2]), "+f"(d[3])
        : "r"(a[0]), "r"(a[1]), "r"(a[2]), "r"(a[3]), "r"(b[0]), "r"(b[1]));
}

// ---------------- kernel: fold 3x3-ternary + 1x1, emit permuted tf32 -----
__global__ void fold_k(const float* __restrict__ w1x1,
                       const float* __restrict__ w_bin) {
    int t = blockIdx.x * 256 + threadIdx.x;
    if (t < C64) { g_sum[t] = 0.0; g_ssq[t] = 0.0; }
    if (t >= 64 * 9 * 64) return;
    int o = t & 63;
    int k = (t >> 6) % 9;        // tap
    int i = t / 576;             // in channel
    float s = 0.f;
    #pragma unroll 8
    for (int m = 0; m < 64; ++m)
        s += w1x1[o * 64 + m] * w_bin[(m * 64 + i) * 9 + k];
    int pl = i >> 5, kk = i & 31, kp = kk >> 4, c16 = kk & 15;
    int slot = (c16 & 3) * 4 + (c16 >> 2);
    g_wB[((pl * 18 + k * 2 + kp) * 64 + o) * 16 + slot] =
        __uint_as_float(tf32_rna(s));
}

// ---------------- kernel: zero padded border ----------------
__global__ void pad_zero() {
    int p = blockIdx.x;      // 0..899
    int b = blockIdx.y;
    int hp, wp;
    if (p < 226)      { hp = 0;   wp = p; }
    else if (p < 452) { hp = 225; wp = p - 226; }
    else { int q = p - 452; hp = 1 + (q >> 1); wp = (q & 1) * 225; }
    g_xpad[(((size_t)b * HP + hp) * HP + wp) * 64 + threadIdx.x] = 0.f;
}

// ---------------- kernel: NCHW -> padded NHWC, tf32-rounded, permuted ----
__global__ void pad_tr(const float* __restrict__ x) {
    __shared__ float s[64][33];
    int lx = threadIdx.x, ly = threadIdx.y;   // 32, 8
    int w0 = blockIdx.x * 32, h = blockIdx.y, b = blockIdx.z;
    #pragma unroll
    for (int i = 0; i < 8; ++i) {
        int c = i * 8 + ly;
        s[c][lx] = x[(((size_t)b * 64 + c) * HW + h) * HW + w0 + lx];
    }
    __syncthreads();
    float* dst = g_xpad + (((size_t)b * HP + h + 1) * HP + w0 + 1) * 64;
    #pragma unroll
    for (int jj = 0; jj < 8; ++jj) {
        int f = jj * 256 + ly * 32 + lx;
        int ch = f & 63, px = f >> 6;
        dst[(size_t)px * 64 + PERM16(ch)] = __uint_as_float(tf32_rna(s[ch][px]));
    }
}

// ---------------- kernel: tf32 mma.sync implicit-GEMM conv + BN stats ----
// Persistent 148 CTAs x 256 thr. Tile D[128px x 64oc], K = 9 taps x 64 ch.
// Warps 4(m) x 2(n); warp tile 32x32. Fragments via LDS.128 (permuted k).
__global__ __launch_bounds__(256, 1)
void conv_mma(const float* __restrict__ bias, float* __restrict__ out) {
    extern __shared__ __align__(16) float sm[];
    float* Bs = sm + SM_B;
    float* As = sm + SM_A;
    const int tid = threadIdx.x;
    const int lane = tid & 31, wid = tid >> 5;
    const int wm = wid & 3, wn = wid >> 2;
    const int gr = lane >> 2, gc = lane & 3;

    // weights + bias -> SMEM once; zero reduction slots
    for (int i = tid; i < 9216; i += 256)
        ((float4*)Bs)[i] = ((const float4*)g_wB)[i];
    if (tid < 64) sm[SM_BIAS + tid] = bias[tid];
    if (tid < 128) sm[SM_RED + tid] = 0.f;

    float ps[4][2], qs[4][2];   // per-thread BN partials (8 fixed o-slots)
    #pragma unroll
    for (int ns = 0; ns < 4; ++ns)
        ps[ns][0] = ps[ns][1] = qs[ns][0] = qs[ns][1] = 0.f;

    for (int j = 0; j < 25; ++j) {
        int t = j * NCTA + blockIdx.x;
        if (t >= NTILE) break;
        int b  = t / 448, rr = t % 448;
        int h  = rr >> 1, w0 = (rr & 1) * 96;
        const float* xrow = g_xpad + (((size_t)b * HP + h) * HP + w0) * 64;

        float acc[2][4][4];
        #pragma unroll
        for (int ms = 0; ms < 2; ++ms)
            #pragma unroll
            for (int ns = 0; ns < 4; ++ns)
                #pragma unroll
                for (int q = 0; q < 4; ++q) acc[ms][ns][q] = 0.f;

        #pragma unroll
        for (int pl = 0; pl < 2; ++pl) {
            __syncthreads();   // previous readers done
            // stage A: 3 rows x 130 px x 32 ch (permuted), px stride 48
            for (int i = tid; i < 3120; i += 256) {
                int r = i / 1040, rem = i % 1040;
                int px = rem >> 3, c4 = rem & 7;
                float4 v = *(const float4*)(xrow + ((size_t)r * HP + px) * 64
                                            + pl * 32 + c4 * 4);
                *(float4*)&As[r * AROW + px * PXS + c4 * 4] = v;
            }
            __syncthreads();

            #pragma unroll
            for (int kh = 0; kh < 3; ++kh) {
                #pragma unroll
                for (int kw = 0; kw < 3; ++kw) {
                    #pragma unroll
                    for (int kp = 0; kp < 2; ++kp) {
                        uint32_t Ae[2][4], Ao[2][4];
                        #pragma unroll
                        for (int ms = 0; ms < 2; ++ms) {
                            const float* ap = As + kh * AROW
                                + (wm * 32 + ms * 16 + gr + kw) * PXS
                                + kp * 16 + gc * 4;
                            float4 lo = *(const float4*)ap;
                            float4 hi = *(const float4*)(ap + 8 * PXS);
                            Ae[ms][0] = fu(lo.x); Ae[ms][1] = fu(hi.x);
                            Ae[ms][2] = fu(lo.y); Ae[ms][3] = fu(hi.y);
                            Ao[ms][0] = fu(lo.z); Ao[ms][1] = fu(hi.z);
                            Ao[ms][2] = fu(lo.w); Ao[ms][3] = fu(hi.w);
                        }
                        const float* bp = Bs
                            + ((pl * 18 + (kh * 3 + kw) * 2 + kp) * 64
                               + wn * 32 + gr) * 16 + gc * 4;
                        #pragma unroll
                        for (int ns = 0; ns < 4; ++ns) {
                            float4 bv = *(const float4*)(bp + ns * 128);
                            uint32_t Be[2] = { fu(bv.x), fu(bv.y) };
                            uint32_t Bo[2] = { fu(bv.z), fu(bv.w) };
                            mma8(acc[0][ns], Ae[0], Be);
                            mma8(acc[1][ns], Ae[1], Be);
                            mma8(acc[0][ns], Ao[0], Bo);
                            mma8(acc[1][ns], Ao[1], Bo);
                        }
                    }
                }
            }
        }

        // epilogue: + bias, NCHW store, BN partials (skip 32-px overlap)
        const size_t chstr = (size_t)HW * HW;
        const int pxb = w0 + wm * 32 + gr;
        const int ob  = wn * 32 + gc * 2;
        const bool cnt = (w0 == 0) | (wm != 0);
        float* obase = out + ((size_t)b * 64) * chstr + (size_t)h * HW;
        #pragma unroll
        for (int ms = 0; ms < 2; ++ms) {
            #pragma unroll
            for (int ns = 0; ns < 4; ++ns) {
                int o0 = ob + ns * 8;
                float b0 = sm[SM_BIAS + o0], b1 = sm[SM_BIAS + o0 + 1];
                float y0 = acc[ms][ns][0] + b0;
                float y1 = acc[ms][ns][1] + b1;
                float y2 = acc[ms][ns][2] + b0;
                float y3 = acc[ms][ns][3] + b1;
                float* p = obase + (size_t)o0 * chstr + pxb + ms * 16;
                p[0]         = y0;
                p[chstr]     = y1;
                p[8]         = y2;
                p[chstr + 8] = y3;
                if (cnt) {
                    ps[ns][0] += y0 + y2;  qs[ns][0] += y0 * y0 + y2 * y2;
                    ps[ns][1] += y1 + y3;  qs[ns][1] += y1 * y1 + y3 * y3;
                }
            }
        }
    }

    // BN partial reduction: regs -> shared -> global doubles
    #pragma unroll
    for (int ns = 0; ns < 4; ++ns) {
        int o0 = wn * 32 + ns * 8 + gc * 2;
        atomicAdd(&sm[SM_RED + o0],          ps[ns][0]);
        atomicAdd(&sm[SM_RED + o0 + 1],      ps[ns][1]);
        atomicAdd(&sm[SM_RED + 64 + o0],     qs[ns][0]);
        atomicAdd(&sm[SM_RED + 64 + o0 + 1], qs[ns][1]);
    }
    __syncthreads();
    if (tid < 64) {
        atomicAdd(&g_sum[tid], (double)sm[SM_RED + tid]);
        atomicAdd(&g_ssq[tid], (double)sm[SM_RED + 64 + tid]);
    }
}

// ---------------- kernel: finalize BN ----------------
__global__ void stats_k(const float* __restrict__ gamma,
                        const float* __restrict__ beta) {
    int c = threadIdx.x;
    if (c >= C64) return;
    double m = g_sum[c] / (double)NPIX;
    double v = g_ssq[c] / (double)NPIX - m * m;
    float a = gamma[c] * rsqrtf((float)v + EPS_BN);
    g_scale[c] = a;
    g_shift[c] = beta[c] - (float)m * a;
}

// ---------------- kernel: normalize + leaky relu + clamp ----------------
__global__ void act_k(float* __restrict__ out) {
    int idx = blockIdx.x * blockDim.x + threadIdx.x;
    const int total4 = NB * C64 * HW * HW / 4;
    if (idx >= total4) return;
    int plane = (idx * 4) / (HW * HW);
    int c = plane & 63;
    float a = g_scale[c], sh = g_shift[c];
    float4 v = ((float4*)out)[idx];
    float* vp = &v.x;
    #pragma unroll
    for (int p = 0; p < 4; ++p) {
        float y = a * vp[p] + sh;
        y = (y >= 0.f) ? y : LEAK * y;
        y = fminf(fmaxf(y, 0.f), CEILV);
        vp[p] = y;
    }
    ((float4*)out)[idx] = v;
}

// ---------------- launch ----------------
extern "C" void kernel_launch(void* const* d_in, const int* in_sizes, int n_in,
                              void* d_out, int out_size) {
    const float* x     = (const float*)d_in[0];
    const float* w_bin = (const float*)d_in[1];
    const float* w1x1  = (const float*)d_in[2];
    const float* b1x1  = (const float*)d_in[3];
    const float* gamma = (const float*)d_in[4];
    const float* beta  = (const float*)d_in[5];
    float* out = (float*)d_out;

    cudaFuncSetAttribute(conv_mma, cudaFuncAttributeMaxDynamicSharedMemorySize,
                         SMEM_DYN);

    fold_k<<<(64 * 9 * 64 + 255) / 256, 256>>>(w1x1, w_bin);
    pad_zero<<<dim3(900, NB), 64>>>();
    pad_tr<<<dim3(7, HW, NB), dim3(32, 8)>>>(x);
    conv_mma<<<NCTA, 256, SMEM_DYN>>>(b1x1, out);
    stats_k<<<1, 64>>>(gamma, beta);
    int total4 = NB * C64 * HW * HW / 4;
    act_k<<<(total4 + 255) / 256, 256>>>(out);
}